// round 1
// baseline (speedup 1.0000x reference)
#include <cuda_runtime.h>

#define NT 4096   // tokens
#define DM 1024   // model dim
#define DF 4096   // ffn dim

// ---- scratch (static device allocations; allowed under _HX_ENFORCE) ----
__device__ float g_Q[NT * DM];
__device__ float g_K[NT * DM];
__device__ float g_V[NT * DM];
__device__ float g_S[(size_t)NT * NT];   // attention scores / probs (64 MB)
__device__ float g_AE[NT * DM];          // attn @ V
__device__ float g_X[NT * DM];           // layernorm output
__device__ float g_H[(size_t)NT * DF];   // ffn hidden (64 MB)

// ---------------------------------------------------------------------------
// Generic 128x128x16 fp32 tiled GEMM, 256 threads, 8x8 per-thread microtile.
//   C[M,N] = alpha * A[M,K] @ B  (+ bias) (+ relu)
//   TRANSB:      B is [N,K] row-major (computes A @ B^T)  -- used for Q@K^T
//   CAUSAL_SKIP: skip output blocks entirely above the diagonal (M==N grid)
//   TRI_K:       K-loop only up to end of this block-row (A is lower-tri)
// ---------------------------------------------------------------------------
template <bool TRANSB, bool CAUSAL_SKIP, bool TRI_K, bool RELU, bool BIAS>
__global__ __launch_bounds__(256, 2)
void gemm128(const float* __restrict__ A, const float* __restrict__ B,
             const float* __restrict__ bias, float* __restrict__ C,
             int M, int N, int K, float alpha)
{
    const int BM = 128, BN = 128, BK = 16;
    __shared__ float As[BK][BM + 4];
    __shared__ float Bs[BK][BN + 4];

    const int bx = blockIdx.x, by = blockIdx.y;
    if (CAUSAL_SKIP && bx > by) return;   // block fully above causal diagonal

    const int tid = threadIdx.x;
    const int tx = tid & 15;
    const int ty = tid >> 4;

    int kEnd = K;
    if (TRI_K) {
        int lim = (by + 1) * BM;
        kEnd = lim < K ? lim : K;
    }

    float acc[8][8];
#pragma unroll
    for (int i = 0; i < 8; i++)
#pragma unroll
        for (int j = 0; j < 8; j++) acc[i][j] = 0.f;

    for (int k0 = 0; k0 < kEnd; k0 += BK) {
        // ---- load A tile (transposed into As[k][m]) and B tile ----
#pragma unroll
        for (int i = 0; i < 2; i++) {
            int idx = tid + i * 256;
            int r = idx >> 2;            // 0..127
            int c = (idx & 3) * 4;       // 0,4,8,12
            float4 va = *(const float4*)(A + (size_t)(by * BM + r) * K + k0 + c);
            As[c + 0][r] = va.x; As[c + 1][r] = va.y;
            As[c + 2][r] = va.z; As[c + 3][r] = va.w;
            if (TRANSB) {
                float4 vb = *(const float4*)(B + (size_t)(bx * BN + r) * K + k0 + c);
                Bs[c + 0][r] = vb.x; Bs[c + 1][r] = vb.y;
                Bs[c + 2][r] = vb.z; Bs[c + 3][r] = vb.w;
            } else {
                int br = idx >> 5;           // 0..15
                int bc = (idx & 31) * 4;     // 0..124
                *(float4*)(&Bs[br][bc]) =
                    *(const float4*)(B + (size_t)(k0 + br) * N + bx * BN + bc);
            }
        }
        __syncthreads();

#pragma unroll
        for (int kk = 0; kk < BK; kk++) {
            float a[8], b[8];
            *(float4*)(a)     = *(const float4*)(&As[kk][ty * 8]);
            *(float4*)(a + 4) = *(const float4*)(&As[kk][ty * 8 + 4]);
            *(float4*)(b)     = *(const float4*)(&Bs[kk][tx * 8]);
            *(float4*)(b + 4) = *(const float4*)(&Bs[kk][tx * 8 + 4]);
#pragma unroll
            for (int i = 0; i < 8; i++)
#pragma unroll
                for (int j = 0; j < 8; j++)
                    acc[i][j] += a[i] * b[j];
        }
        __syncthreads();
    }

    // ---- epilogue ----
    float bb[8];
    if (BIAS) {
#pragma unroll
        for (int j = 0; j < 8; j++) bb[j] = bias[bx * BN + tx * 8 + j];
    }
#pragma unroll
    for (int i = 0; i < 8; i++) {
        int row = by * BM + ty * 8 + i;
        float out[8];
#pragma unroll
        for (int j = 0; j < 8; j++) {
            float v = acc[i][j] * alpha;
            if (BIAS) v += bb[j];
            if (RELU) v = v > 0.f ? v : 0.f;
            out[j] = v;
        }
        *(float4*)(C + (size_t)row * N + bx * BN + tx * 8)     = *(float4*)(out);
        *(float4*)(C + (size_t)row * N + bx * BN + tx * 8 + 4) = *(float4*)(out + 4);
    }
}

// ---------------------------------------------------------------------------
// Causal softmax over row r of S (length r+1 valid). Writes zeros for the
// masked entries up to the 128-aligned boundary so the A@V GEMM can use a
// triangular K-loop. One block (256 threads) per row; values stay in regs.
// ---------------------------------------------------------------------------
__global__ void softmax_causal(float* __restrict__ S)
{
    const int r = blockIdx.x;
    const int tid = threadIdx.x;
    const int limit = ((r >> 7) + 1) << 7;   // round (r+1) up to 128
    float* row = S + (size_t)r * NT;

    float vals[16];                           // limit/256 <= 16
    int n = 0;
    float m = -1e30f;
    for (int j = tid; j < limit; j += 256) {
        float v = (j <= r) ? row[j] : -1e30f;
        vals[n++] = v;
        m = fmaxf(m, v);
    }

    __shared__ float redm[8];
    __shared__ float reds[8];
#pragma unroll
    for (int o = 16; o > 0; o >>= 1)
        m = fmaxf(m, __shfl_xor_sync(0xffffffffu, m, o));
    if ((tid & 31) == 0) redm[tid >> 5] = m;
    __syncthreads();
    m = redm[0];
#pragma unroll
    for (int i = 1; i < 8; i++) m = fmaxf(m, redm[i]);

    float s = 0.f;
    for (int i = 0; i < n; i++) {
        float e = __expf(vals[i] - m);   // masked (-1e30) entries underflow to 0
        vals[i] = e;
        s += e;
    }
#pragma unroll
    for (int o = 16; o > 0; o >>= 1)
        s += __shfl_xor_sync(0xffffffffu, s, o);
    if ((tid & 31) == 0) reds[tid >> 5] = s;
    __syncthreads();
    s = reds[0];
#pragma unroll
    for (int i = 1; i < 8; i++) s += reds[i];

    const float inv = 1.f / s;
    n = 0;
    for (int j = tid; j < limit; j += 256)
        row[j] = vals[n++] * inv;
}

// ---------------------------------------------------------------------------
// x = AE + E; LayerNorm over D=1024 with gamma/beta. One block (256 thr)/row,
// 4 elements per thread (float4).
// ---------------------------------------------------------------------------
__global__ void add_layernorm(const float* __restrict__ AE, const float* __restrict__ E,
                              const float* __restrict__ gamma, const float* __restrict__ beta,
                              float* __restrict__ X)
{
    const int r = blockIdx.x;
    const int tid = threadIdx.x;

    float4 a = ((const float4*)(AE + (size_t)r * DM))[tid];
    float4 e = ((const float4*)(E + (size_t)r * DM))[tid];
    float x0 = a.x + e.x, x1 = a.y + e.y, x2 = a.z + e.z, x3 = a.w + e.w;

    float s = x0 + x1 + x2 + x3;
    float q = x0 * x0 + x1 * x1 + x2 * x2 + x3 * x3;

    __shared__ float rs[8];
    __shared__ float rq[8];
#pragma unroll
    for (int o = 16; o > 0; o >>= 1) {
        s += __shfl_xor_sync(0xffffffffu, s, o);
        q += __shfl_xor_sync(0xffffffffu, q, o);
    }
    if ((tid & 31) == 0) { rs[tid >> 5] = s; rq[tid >> 5] = q; }
    __syncthreads();
    s = rs[0]; q = rq[0];
#pragma unroll
    for (int i = 1; i < 8; i++) { s += rs[i]; q += rq[i]; }

    const float mean = s * (1.f / DM);
    const float var  = q * (1.f / DM) - mean * mean;
    const float inv  = rsqrtf(var + 1e-5f);

    float4 g = ((const float4*)gamma)[tid];
    float4 b = ((const float4*)beta)[tid];
    float4 o;
    o.x = (x0 - mean) * inv * g.x + b.x;
    o.y = (x1 - mean) * inv * g.y + b.y;
    o.z = (x2 - mean) * inv * g.z + b.z;
    o.w = (x3 - mean) * inv * g.w + b.w;
    ((float4*)(X + (size_t)r * DM))[tid] = o;
}

// ---------------------------------------------------------------------------
extern "C" void kernel_launch(void* const* d_in, const int* in_sizes, int n_in,
                              void* d_out, int out_size)
{
    (void)in_sizes; (void)n_in; (void)out_size;
    const float* E     = (const float*)d_in[0];
    const float* Wq    = (const float*)d_in[1];
    const float* bq    = (const float*)d_in[2];
    const float* Wk    = (const float*)d_in[3];
    const float* bk    = (const float*)d_in[4];
    const float* Wv    = (const float*)d_in[5];
    const float* bv    = (const float*)d_in[6];
    const float* gamma = (const float*)d_in[7];
    const float* beta  = (const float*)d_in[8];
    const float* W1    = (const float*)d_in[9];
    const float* b1    = (const float*)d_in[10];
    const float* W2    = (const float*)d_in[11];
    const float* b2    = (const float*)d_in[12];
    float* out = (float*)d_out;

    float *Q, *K, *V, *S, *AE, *X, *H;
    cudaGetSymbolAddress((void**)&Q,  g_Q);
    cudaGetSymbolAddress((void**)&K,  g_K);
    cudaGetSymbolAddress((void**)&V,  g_V);
    cudaGetSymbolAddress((void**)&S,  g_S);
    cudaGetSymbolAddress((void**)&AE, g_AE);
    cudaGetSymbolAddress((void**)&X,  g_X);
    cudaGetSymbolAddress((void**)&H,  g_H);

    dim3 blk(256);
    dim3 gProj(DM / 128, NT / 128);   // 8 x 32
    dim3 gS(NT / 128, NT / 128);      // 32 x 32
    dim3 gF1(DF / 128, NT / 128);     // 32 x 32

    // Q/K/V projections
    gemm128<false, false, false, false, true><<<gProj, blk>>>(E, Wq, bq, Q, NT, DM, DM, 1.f);
    gemm128<false, false, false, false, true><<<gProj, blk>>>(E, Wk, bk, K, NT, DM, DM, 1.f);
    gemm128<false, false, false, false, true><<<gProj, blk>>>(E, Wv, bv, V, NT, DM, DM, 1.f);

    // S = Q @ K^T / sqrt(D), lower-triangle blocks only
    gemm128<true, true, false, false, false><<<gS, blk>>>(Q, K, nullptr, S, NT, NT, DM, 0.03125f);

    // causal softmax (zero-fills masked entries up to 128-aligned boundary)
    softmax_causal<<<NT, 256>>>(S);

    // AE = A @ V with triangular K-loop
    gemm128<false, false, true, false, false><<<gProj, blk>>>(S, V, nullptr, AE, NT, DM, NT, 1.f);

    // x = LayerNorm(AE + E)
    add_layernorm<<<NT, 256>>>(AE, E, gamma, beta, X);

    // FFN
    gemm128<false, false, false, true, true><<<gF1, blk>>>(X, W1, b1, H, NT, DF, DM, 1.f);
    gemm128<false, false, false, false, true><<<gProj, blk>>>(H, W2, b2, out, NT, DM, DF, 1.f);
}

// round 3
// speedup vs baseline: 1.4873x; 1.4873x over previous
#include <cuda_runtime.h>
#include <cstdint>

#define NT 4096   // tokens
#define DM 1024   // model dim
#define DF 4096   // ffn dim

// ---- scratch (static device globals; allowed) ----
__device__ float g_Q[NT * DM];
__device__ float g_K[NT * DM];
__device__ float g_V[NT * DM];
__device__ float g_S[(size_t)NT * NT];
__device__ float g_AE[NT * DM];
__device__ float g_X[NT * DM];
__device__ float g_H[(size_t)NT * DF];
__device__ float g_Wqt[DM * DM];
__device__ float g_Wkt[DM * DM];
__device__ float g_Wvt[DM * DM];
__device__ float g_W1t[(size_t)DM * DF];
__device__ float g_W2t[(size_t)DM * DF];
__device__ float g_Vt[(size_t)NT * DM];

__device__ __forceinline__ uint32_t f2tf32(float f) {
    uint32_t u; asm("cvt.rna.tf32.f32 %0, %1;" : "=r"(u) : "f"(f)); return u;
}

__device__ __forceinline__ void mma_tf32(float* c, const uint32_t* a, const uint32_t* b) {
    asm volatile(
        "mma.sync.aligned.m16n8k8.row.col.f32.tf32.tf32.f32 "
        "{%0,%1,%2,%3}, {%4,%5,%6,%7}, {%8,%9}, {%0,%1,%2,%3};"
        : "+f"(c[0]), "+f"(c[1]), "+f"(c[2]), "+f"(c[3])
        : "r"(a[0]), "r"(a[1]), "r"(a[2]), "r"(a[3]), "r"(b[0]), "r"(b[1]));
}

// ===========================================================================
// tf32 tensor-core GEMM via mma.sync (legacy path, works on plain sm_103).
//   C[M,N] = alpha * A[M,K] @ Bt[N,K]^T (+bias) (+relu)
// Tiles: 128x128x16, 128 threads = 4 warps in 2x2, warp tile 64x64.
// Smem holds operands PRE-PERMUTED into mma fragment layout:
//   A: [ks][mtile][lane][4 regs]   (frag load = one lds.128)
//   B: [ks][ntile][lane][2 regs]   (frag load = one lds.64)
// ===========================================================================
template <bool CAUSAL, bool TRIK, bool RELU, bool BIAS>
__global__ __launch_bounds__(128, 2)
void tc_gemm(const float* __restrict__ A, const float* __restrict__ Bt,
             const float* __restrict__ bias, float* __restrict__ C,
             int N, int Kdim, float alpha)
{
    __shared__ __align__(16) uint32_t As[2][2048];   // 2 bufs x 8KB
    __shared__ __align__(16) uint32_t Bs[2][2048];

    const int bx = blockIdx.x, by = blockIdx.y;
    if (CAUSAL && bx > by) return;

    const int tid  = threadIdx.x;
    const int wid  = tid >> 5;
    const int lane = tid & 31;
    const int g    = lane >> 2;     // group id (row within 8)
    const int tig  = lane & 3;      // thread in group

    const int wmt = (wid >> 1) * 4;  // warp's first mtile (of 8)
    const int wnt = (wid & 1) * 8;   // warp's first ntile (of 16)

    int kEnd = Kdim;
    if (TRIK) { int lim = (by + 1) * 128; kEnd = lim < Kdim ? lim : Kdim; }
    const int niter = kEnd >> 4;

    const float* aptr = A  + ((size_t)by * 128 + tid) * (size_t)Kdim;
    const float* bptr = Bt + ((size_t)bx * 128 + tid) * (size_t)Kdim;

    // permuted-store bases (thread t owns global row t of each tile)
    const int aBase = ((tid >> 4) << 7) + ((tid & 7) << 4) + ((tid >> 3) & 1);
    const int bBase = ((tid >> 3) << 6) + ((tid & 7) << 3);

    float acc[4][8][4];
#pragma unroll
    for (int i = 0; i < 4; i++)
#pragma unroll
        for (int j = 0; j < 8; j++)
#pragma unroll
            for (int q = 0; q < 4; q++) acc[i][j][q] = 0.f;

    float4 ra[4], rb[4];

#define LDG_T(k0) do { \
        _Pragma("unroll") \
        for (int t = 0; t < 4; t++) { \
            ra[t] = *(const float4*)(aptr + (k0) + t * 4); \
            rb[t] = *(const float4*)(bptr + (k0) + t * 4); \
        } } while (0)

    // scatter-store one tile into fragment layout (16 scalars each for A, B)
#define STS_T(buf) do { \
        _Pragma("unroll") \
        for (int t = 0; t < 4; t++) { \
            const float va[4] = { ra[t].x, ra[t].y, ra[t].z, ra[t].w }; \
            const float vb[4] = { rb[t].x, rb[t].y, rb[t].z, rb[t].w }; \
            _Pragma("unroll") \
            for (int j = 0; j < 4; j++) { \
                const int kk  = t * 4 + j; \
                const int ks  = kk >> 3; \
                const int kk7 = kk & 7; \
                As[buf][aBase + ks * 1024 + (kk7 & 3) * 4 + ((kk7 >> 2) << 1)] = f2tf32(va[j]); \
                Bs[buf][bBase + ks * 1024 + (kk7 & 3) * 2 + (kk7 >> 2)]        = f2tf32(vb[j]); \
            } \
        } } while (0)

    LDG_T(0);
    STS_T(0);
    __syncthreads();

    for (int i = 0; i < niter; i++) {
        const int b = i & 1;
        if (i + 1 < niter) LDG_T((i + 1) * 16);

#pragma unroll
        for (int ks = 0; ks < 2; ks++) {
            uint4 af[4];
            uint2 bf[8];
#pragma unroll
            for (int m = 0; m < 4; m++)
                af[m] = *(const uint4*)&As[b][ks * 1024 + (wmt + m) * 128 + lane * 4];
#pragma unroll
            for (int n = 0; n < 8; n++)
                bf[n] = *(const uint2*)&Bs[b][ks * 1024 + (wnt + n) * 64 + lane * 2];
#pragma unroll
            for (int m = 0; m < 4; m++)
#pragma unroll
                for (int n = 0; n < 8; n++)
                    mma_tf32(acc[m][n], (const uint32_t*)&af[m], (const uint32_t*)&bf[n]);
        }

        if (i + 1 < niter) STS_T(b ^ 1);
        __syncthreads();
    }

    // ---- epilogue: direct coalesced float2 stores ----
    const int rowBase = by * 128 + (wid >> 1) * 64 + g;
    const int colBase = bx * 128 + (wid & 1) * 64 + tig * 2;
#pragma unroll
    for (int m = 0; m < 4; m++) {
        const int r0 = rowBase + m * 16;
#pragma unroll
        for (int n = 0; n < 8; n++) {
            const int col = colBase + n * 8;
            float b0 = 0.f, b1 = 0.f;
            if (BIAS) { b0 = bias[col]; b1 = bias[col + 1]; }
            float2 v0, v1;
            v0.x = acc[m][n][0] * alpha + b0;
            v0.y = acc[m][n][1] * alpha + b1;
            v1.x = acc[m][n][2] * alpha + b0;
            v1.y = acc[m][n][3] * alpha + b1;
            if (RELU) {
                v0.x = fmaxf(v0.x, 0.f); v0.y = fmaxf(v0.y, 0.f);
                v1.x = fmaxf(v1.x, 0.f); v1.y = fmaxf(v1.y, 0.f);
            }
            *(float2*)(C + (size_t)r0 * N + col)       = v0;
            *(float2*)(C + (size_t)(r0 + 8) * N + col) = v1;
        }
    }
#undef LDG_T
#undef STS_T
}

// ======================= transpose: out[C][R] = in[R][C]^T =======================
__global__ void transpose_k(const float* __restrict__ in, float* __restrict__ out,
                            int R, int C)
{
    __shared__ float t[32][33];
    const int bc = blockIdx.x * 32;
    const int br = blockIdx.y * 32;
    const int x = threadIdx.x, y = threadIdx.y;
#pragma unroll
    for (int j = 0; j < 32; j += 8)
        t[y + j][x] = in[(size_t)(br + y + j) * C + bc + x];
    __syncthreads();
#pragma unroll
    for (int j = 0; j < 32; j += 8)
        out[(size_t)(bc + y + j) * R + br + x] = t[x][y + j];
}

// ======================= causal softmax =======================
__global__ void softmax_causal(float* __restrict__ S)
{
    const int r = blockIdx.x;
    const int tid = threadIdx.x;
    const int limit = ((r >> 7) + 1) << 7;
    float* row = S + (size_t)r * NT;

    float vals[16];
    int n = 0;
    float m = -1e30f;
    for (int j = tid; j < limit; j += 256) {
        float v = (j <= r) ? row[j] : -1e30f;
        vals[n++] = v;
        m = fmaxf(m, v);
    }
    __shared__ float redm[8], reds[8];
#pragma unroll
    for (int o = 16; o > 0; o >>= 1) m = fmaxf(m, __shfl_xor_sync(0xffffffffu, m, o));
    if ((tid & 31) == 0) redm[tid >> 5] = m;
    __syncthreads();
    m = redm[0];
#pragma unroll
    for (int i = 1; i < 8; i++) m = fmaxf(m, redm[i]);

    float s = 0.f;
    for (int i = 0; i < n; i++) { float e = __expf(vals[i] - m); vals[i] = e; s += e; }
#pragma unroll
    for (int o = 16; o > 0; o >>= 1) s += __shfl_xor_sync(0xffffffffu, s, o);
    if ((tid & 31) == 0) reds[tid >> 5] = s;
    __syncthreads();
    s = reds[0];
#pragma unroll
    for (int i = 1; i < 8; i++) s += reds[i];

    const float inv = 1.f / s;
    n = 0;
    for (int j = tid; j < limit; j += 256) row[j] = vals[n++] * inv;
}

// ======================= add + LayerNorm =======================
__global__ void add_layernorm(const float* __restrict__ AE, const float* __restrict__ E,
                              const float* __restrict__ gamma, const float* __restrict__ beta,
                              float* __restrict__ X)
{
    const int r = blockIdx.x;
    const int tid = threadIdx.x;
    float4 a = ((const float4*)(AE + (size_t)r * DM))[tid];
    float4 e = ((const float4*)(E + (size_t)r * DM))[tid];
    float x0 = a.x + e.x, x1 = a.y + e.y, x2 = a.z + e.z, x3 = a.w + e.w;
    float s = x0 + x1 + x2 + x3;
    float q = x0 * x0 + x1 * x1 + x2 * x2 + x3 * x3;
    __shared__ float rs[8], rq[8];
#pragma unroll
    for (int o = 16; o > 0; o >>= 1) {
        s += __shfl_xor_sync(0xffffffffu, s, o);
        q += __shfl_xor_sync(0xffffffffu, q, o);
    }
    if ((tid & 31) == 0) { rs[tid >> 5] = s; rq[tid >> 5] = q; }
    __syncthreads();
    s = rs[0]; q = rq[0];
#pragma unroll
    for (int i = 1; i < 8; i++) { s += rs[i]; q += rq[i]; }
    const float mean = s * (1.f / DM);
    const float var  = q * (1.f / DM) - mean * mean;
    const float inv  = rsqrtf(var + 1e-5f);
    float4 gg = ((const float4*)gamma)[tid];
    float4 bb = ((const float4*)beta)[tid];
    float4 o;
    o.x = (x0 - mean) * inv * gg.x + bb.x;
    o.y = (x1 - mean) * inv * gg.y + bb.y;
    o.z = (x2 - mean) * inv * gg.z + bb.z;
    o.w = (x3 - mean) * inv * gg.w + bb.w;
    ((float4*)(X + (size_t)r * DM))[tid] = o;
}

// ======================= launch =======================
extern "C" void kernel_launch(void* const* d_in, const int* in_sizes, int n_in,
                              void* d_out, int out_size)
{
    (void)in_sizes; (void)n_in; (void)out_size;
    const float* E     = (const float*)d_in[0];
    const float* Wq    = (const float*)d_in[1];
    const float* bq    = (const float*)d_in[2];
    const float* Wk    = (const float*)d_in[3];
    const float* bk    = (const float*)d_in[4];
    const float* Wv    = (const float*)d_in[5];
    const float* bv    = (const float*)d_in[6];
    const float* gamma = (const float*)d_in[7];
    const float* beta  = (const float*)d_in[8];
    const float* W1    = (const float*)d_in[9];
    const float* b1    = (const float*)d_in[10];
    const float* W2    = (const float*)d_in[11];
    const float* b2    = (const float*)d_in[12];
    float* out = (float*)d_out;

    float *Q, *K, *V, *S, *AE, *X, *H, *Wqt, *Wkt, *Wvt, *W1t, *W2t, *Vt;
    cudaGetSymbolAddress((void**)&Q,   g_Q);
    cudaGetSymbolAddress((void**)&K,   g_K);
    cudaGetSymbolAddress((void**)&V,   g_V);
    cudaGetSymbolAddress((void**)&S,   g_S);
    cudaGetSymbolAddress((void**)&AE,  g_AE);
    cudaGetSymbolAddress((void**)&X,   g_X);
    cudaGetSymbolAddress((void**)&H,   g_H);
    cudaGetSymbolAddress((void**)&Wqt, g_Wqt);
    cudaGetSymbolAddress((void**)&Wkt, g_Wkt);
    cudaGetSymbolAddress((void**)&Wvt, g_Wvt);
    cudaGetSymbolAddress((void**)&W1t, g_W1t);
    cudaGetSymbolAddress((void**)&W2t, g_W2t);
    cudaGetSymbolAddress((void**)&Vt,  g_Vt);

    dim3 tb(32, 8);
    transpose_k<<<dim3(DM / 32, DM / 32), tb>>>(Wq, Wqt, DM, DM);
    transpose_k<<<dim3(DM / 32, DM / 32), tb>>>(Wk, Wkt, DM, DM);
    transpose_k<<<dim3(DM / 32, DM / 32), tb>>>(Wv, Wvt, DM, DM);
    transpose_k<<<dim3(DF / 32, DM / 32), tb>>>(W1, W1t, DM, DF);
    transpose_k<<<dim3(DM / 32, DF / 32), tb>>>(W2, W2t, DF, DM);

    dim3 blk(128);
    dim3 gProj(DM / 128, NT / 128);   // 8 x 32
    dim3 gS(NT / 128, NT / 128);      // 32 x 32
    dim3 gF1(DF / 128, NT / 128);     // 32 x 32

    // QKV projections
    tc_gemm<false, false, false, true><<<gProj, blk>>>(E, Wqt, bq, Q, DM, DM, 1.f);
    tc_gemm<false, false, false, true><<<gProj, blk>>>(E, Wkt, bk, K, DM, DM, 1.f);
    tc_gemm<false, false, false, true><<<gProj, blk>>>(E, Wvt, bv, V, DM, DM, 1.f);

    // S = Q @ K^T / 32 (lower-triangle blocks only)
    tc_gemm<true, false, false, false><<<gS, blk>>>(Q, K, nullptr, S, NT, DM, 0.03125f);

    softmax_causal<<<NT, 256>>>(S);

    // AE = A @ V (B operand = V^T, triangular K)
    transpose_k<<<dim3(DM / 32, NT / 32), tb>>>(V, Vt, NT, DM);
    tc_gemm<false, true, false, false><<<gProj, blk>>>(S, Vt, nullptr, AE, DM, NT, 1.f);

    add_layernorm<<<NT, 256>>>(AE, E, gamma, beta, X);

    // FFN
    tc_gemm<false, false, true, true><<<gF1, blk>>>(X, W1t, b1, H, DF, DM, 1.f);
    tc_gemm<false, false, false, true><<<gProj, blk>>>(H, W2t, b2, out, DM, DF, 1.f);
}

// round 4
// speedup vs baseline: 1.9067x; 1.2820x over previous
#include <cuda_runtime.h>
#include <cstdint>

#define NT 4096   // tokens
#define DM 1024   // model dim
#define DF 4096   // ffn dim

// ---- scratch (static device globals; allowed) ----
__device__ float g_Q[NT * DM];
__device__ float g_K[NT * DM];
__device__ float g_V[NT * DM];
__device__ float g_S[(size_t)NT * NT];
__device__ float g_AE[NT * DM];
__device__ float g_X[NT * DM];
__device__ float g_H[(size_t)NT * DF];
__device__ float g_Wqt[DM * DM];
__device__ float g_Wkt[DM * DM];
__device__ float g_Wvt[DM * DM];
__device__ float g_W1t[(size_t)DM * DF];
__device__ float g_W2t[(size_t)DM * DF];
__device__ float g_Vt[(size_t)NT * DM];

__device__ __forceinline__ uint32_t f2tf32(float f) {
    uint32_t u; asm("cvt.rna.tf32.f32 %0, %1;" : "=r"(u) : "f"(f)); return u;
}
__device__ __forceinline__ uint32_t smem_u32(const void* p) {
    uint32_t a;
    asm("{ .reg .u64 t; cvta.to.shared.u64 t, %1; cvt.u32.u64 %0, t; }" : "=r"(a) : "l"(p));
    return a;
}
__device__ __forceinline__ void mma_tf32(float* c, const uint32_t* a, const uint32_t* b) {
    asm volatile(
        "mma.sync.aligned.m16n8k8.row.col.f32.tf32.tf32.f32 "
        "{%0,%1,%2,%3}, {%4,%5,%6,%7}, {%8,%9}, {%0,%1,%2,%3};"
        : "+f"(c[0]), "+f"(c[1]), "+f"(c[2]), "+f"(c[3])
        : "r"(a[0]), "r"(a[1]), "r"(a[2]), "r"(a[3]), "r"(b[0]), "r"(b[1]));
}
__device__ __forceinline__ void ldsm4(uint32_t& r0, uint32_t& r1, uint32_t& r2, uint32_t& r3,
                                      uint32_t addr) {
    asm volatile("ldmatrix.sync.aligned.m8n8.x4.shared.b16 {%0,%1,%2,%3}, [%4];"
                 : "=r"(r0), "=r"(r1), "=r"(r2), "=r"(r3) : "r"(addr));
}

// ===========================================================================
// tf32 mma.sync GEMM.  C[M,N] = alpha * A[M,K] @ Bt[N,K]^T (+bias) (+relu)
// Tiles 128x128x16, 128 threads (4 warps, 2x2 -> 64x64 warp tiles).
// Smem: row-major tiles, 16 tf32 (4x16B chunks) per row, XOR-swizzled
//   chunk placement c_phys = c ^ ((row>>1)&3)  -> conflict-free STS.128
//   AND conflict-free ldmatrix (per-8-row bank bijection).
// Fragments loaded via ldmatrix.x4.b16 (8-row x 16B tile == tf32 8x4 frag).
// ===========================================================================
template <bool CAUSAL, bool TRIK, bool RELU, bool BIAS>
__global__ __launch_bounds__(128, 2)
void tc_gemm(const float* __restrict__ A, const float* __restrict__ Bt,
             const float* __restrict__ bias, float* __restrict__ C,
             int N, int Kdim, float alpha)
{
    __shared__ __align__(16) uint32_t As[2][2048];   // 2 bufs x 128 rows x 16 words
    __shared__ __align__(16) uint32_t Bs[2][2048];

    const int bx = blockIdx.x, by = blockIdx.y;
    if (CAUSAL && bx > by) return;

    const int tid  = threadIdx.x;
    const int wid  = tid >> 5;
    const int lane = tid & 31;
    const int g    = lane >> 2;
    const int tig  = lane & 3;
    const int l7   = lane & 7;
    const int q    = lane >> 3;          // ldmatrix matrix index 0..3

    const int wmt = (wid >> 1) * 4;      // first mtile (m16 units) of warp
    const int wnt = (wid & 1) * 8;       // first ntile (n8 units) of warp

    int kEnd = Kdim;
    if (TRIK) { int lim = (by + 1) * 128; kEnd = lim < Kdim ? lim : Kdim; }
    const int niter = kEnd >> 4;

    const float* aptr = A  + ((size_t)by * 128 + tid) * (size_t)Kdim;
    const float* bptr = Bt + ((size_t)bx * 128 + tid) * (size_t)Kdim;

    const uint32_t aSm = smem_u32(As);
    const uint32_t bSm = smem_u32(Bs);
    const int swt = (tid >> 1) & 3;      // store-side swizzle for this thread's row

    // ldmatrix per-lane address components (row fixed per m/p; chunk varies w/ ks)
    // A mtile m: row = (wmt+m)*16 + (q&1)*8 + l7, chunk = 2ks + (q>>1)
    // B pair  p: row = (wnt+2p+(q>>1))*8 + l7,   chunk = 2ks + (q&1)
    uint32_t aRow[4], aSw[4], bRow[4], bSw[4];
#pragma unroll
    for (int m = 0; m < 4; m++) {
        int r = (wmt + m) * 16 + (q & 1) * 8 + l7;
        aRow[m] = (uint32_t)r * 64u;
        aSw[m]  = (uint32_t)((r >> 1) & 3);
    }
#pragma unroll
    for (int p = 0; p < 4; p++) {
        int r = (wnt + 2 * p + (q >> 1)) * 8 + l7;
        bRow[p] = (uint32_t)r * 64u;
        bSw[p]  = (uint32_t)((r >> 1) & 3);
    }
    const uint32_t aQhi = (uint32_t)(q >> 1);   // A chunk low bit
    const uint32_t bQlo = (uint32_t)(q & 1);    // B chunk low bit

    float acc[4][8][4];
#pragma unroll
    for (int i = 0; i < 4; i++)
#pragma unroll
        for (int j = 0; j < 8; j++)
#pragma unroll
            for (int t = 0; t < 4; t++) acc[i][j][t] = 0.f;

    float4 ra[4], rb[4];

#define LDG_T(k0) do { \
        _Pragma("unroll") \
        for (int t = 0; t < 4; t++) { \
            ra[t] = *(const float4*)(aptr + (k0) + t * 4); \
            rb[t] = *(const float4*)(bptr + (k0) + t * 4); \
        } } while (0)

#define STS_T(buf) do { \
        _Pragma("unroll") \
        for (int t = 0; t < 4; t++) { \
            uint4 wa, wb; \
            wa.x = f2tf32(ra[t].x); wa.y = f2tf32(ra[t].y); \
            wa.z = f2tf32(ra[t].z); wa.w = f2tf32(ra[t].w); \
            wb.x = f2tf32(rb[t].x); wb.y = f2tf32(rb[t].y); \
            wb.z = f2tf32(rb[t].z); wb.w = f2tf32(rb[t].w); \
            const int wi = tid * 16 + ((t ^ swt) << 2); \
            *(uint4*)&As[buf][wi] = wa; \
            *(uint4*)&Bs[buf][wi] = wb; \
        } } while (0)

    LDG_T(0);
    STS_T(0);
    __syncthreads();

    for (int i = 0; i < niter; i++) {
        const int b = i & 1;
        if (i + 1 < niter) LDG_T((i + 1) * 16);

        const uint32_t aBase = aSm + (uint32_t)b * 8192u;
        const uint32_t bBase = bSm + (uint32_t)b * 8192u;
#pragma unroll
        for (int ks = 0; ks < 2; ks++) {
            uint32_t af[4][4], bf[8][2];
#pragma unroll
            for (int m = 0; m < 4; m++) {
                uint32_t c = (uint32_t)(2 * ks) + aQhi;
                ldsm4(af[m][0], af[m][1], af[m][2], af[m][3],
                      aBase + aRow[m] + ((c ^ aSw[m]) << 4));
            }
#pragma unroll
            for (int p = 0; p < 4; p++) {
                uint32_t c = (uint32_t)(2 * ks) + bQlo;
                ldsm4(bf[2 * p][0], bf[2 * p][1], bf[2 * p + 1][0], bf[2 * p + 1][1],
                      bBase + bRow[p] + ((c ^ bSw[p]) << 4));
            }
#pragma unroll
            for (int m = 0; m < 4; m++)
#pragma unroll
                for (int n = 0; n < 8; n++)
                    mma_tf32(acc[m][n], af[m], bf[n]);
        }

        if (i + 1 < niter) STS_T(b ^ 1);
        __syncthreads();
    }

    // ---- epilogue: direct float2 stores ----
    const int rowBase = by * 128 + (wid >> 1) * 64 + g;
    const int colBase = bx * 128 + (wid & 1) * 64 + tig * 2;
#pragma unroll
    for (int m = 0; m < 4; m++) {
        const int r0 = rowBase + m * 16;
#pragma unroll
        for (int n = 0; n < 8; n++) {
            const int col = colBase + n * 8;
            float b0 = 0.f, b1 = 0.f;
            if (BIAS) { b0 = bias[col]; b1 = bias[col + 1]; }
            float2 v0, v1;
            v0.x = acc[m][n][0] * alpha + b0;
            v0.y = acc[m][n][1] * alpha + b1;
            v1.x = acc[m][n][2] * alpha + b0;
            v1.y = acc[m][n][3] * alpha + b1;
            if (RELU) {
                v0.x = fmaxf(v0.x, 0.f); v0.y = fmaxf(v0.y, 0.f);
                v1.x = fmaxf(v1.x, 0.f); v1.y = fmaxf(v1.y, 0.f);
            }
            *(float2*)(C + (size_t)r0 * N + col)       = v0;
            *(float2*)(C + (size_t)(r0 + 8) * N + col) = v1;
        }
    }
#undef LDG_T
#undef STS_T
}

// ======================= transpose: out[C][R] = in[R][C]^T =======================
__global__ void transpose_k(const float* __restrict__ in, float* __restrict__ out,
                            int R, int C)
{
    __shared__ float t[32][33];
    const int bc = blockIdx.x * 32;
    const int br = blockIdx.y * 32;
    const int x = threadIdx.x, y = threadIdx.y;
#pragma unroll
    for (int j = 0; j < 32; j += 8)
        t[y + j][x] = in[(size_t)(br + y + j) * C + bc + x];
    __syncthreads();
#pragma unroll
    for (int j = 0; j < 32; j += 8)
        out[(size_t)(bc + y + j) * R + br + x] = t[x][y + j];
}

// ======================= fast exp (FMA pipe, no MUFU) =======================
__device__ __forceinline__ float fast_exp(float x) {
    float y = x * 1.4426950408889634f;        // log2(e)
    float n = rintf(y);
    float f = y - n;                           // f in [-0.5, 0.5]
    // 2^f = e^(f ln2), Taylor deg-6 (max rel err ~1e-7 on the interval)
    float p = 1.5403530393e-4f;
    p = fmaf(p, f, 1.3333558146e-3f);
    p = fmaf(p, f, 9.6181291076e-3f);
    p = fmaf(p, f, 5.5504108665e-2f);
    p = fmaf(p, f, 2.4022650696e-1f);
    p = fmaf(p, f, 6.9314718056e-1f);
    p = fmaf(p, f, 1.0f);
    float ec = fmaxf(n, -126.f);               // clamp (masked -1e30 -> ~0)
    return __int_as_float(((int)ec + 127) << 23) * p;
}

// ======================= causal softmax =======================
__global__ void softmax_causal(float* __restrict__ S)
{
    const int r = blockIdx.x;
    const int tid = threadIdx.x;
    const int limit = ((r >> 7) + 1) << 7;
    float* row = S + (size_t)r * NT;

    float vals[16];
    int n = 0;
    float m = -1e30f;
    for (int j = tid; j < limit; j += 256) {
        float v = (j <= r) ? row[j] : -1e30f;
        vals[n++] = v;
        m = fmaxf(m, v);
    }
    __shared__ float redm[8], reds[8];
#pragma unroll
    for (int o = 16; o > 0; o >>= 1) m = fmaxf(m, __shfl_xor_sync(0xffffffffu, m, o));
    if ((tid & 31) == 0) redm[tid >> 5] = m;
    __syncthreads();
    m = redm[0];
#pragma unroll
    for (int i = 1; i < 8; i++) m = fmaxf(m, redm[i]);

    float s = 0.f;
    for (int i = 0; i < n; i++) { float e = fast_exp(vals[i] - m); vals[i] = e; s += e; }
#pragma unroll
    for (int o = 16; o > 0; o >>= 1) s += __shfl_xor_sync(0xffffffffu, s, o);
    if ((tid & 31) == 0) reds[tid >> 5] = s;
    __syncthreads();
    s = reds[0];
#pragma unroll
    for (int i = 1; i < 8; i++) s += reds[i];

    const float inv = 1.f / s;
    n = 0;
    for (int j = tid; j < limit; j += 256) row[j] = vals[n++] * inv;
}

// ======================= add + LayerNorm =======================
__global__ void add_layernorm(const float* __restrict__ AE, const float* __restrict__ E,
                              const float* __restrict__ gamma, const float* __restrict__ beta,
                              float* __restrict__ X)
{
    const int r = blockIdx.x;
    const int tid = threadIdx.x;
    float4 a = ((const float4*)(AE + (size_t)r * DM))[tid];
    float4 e = ((const float4*)(E + (size_t)r * DM))[tid];
    float x0 = a.x + e.x, x1 = a.y + e.y, x2 = a.z + e.z, x3 = a.w + e.w;
    float s = x0 + x1 + x2 + x3;
    float q = x0 * x0 + x1 * x1 + x2 * x2 + x3 * x3;
    __shared__ float rs[8], rq[8];
#pragma unroll
    for (int o = 16; o > 0; o >>= 1) {
        s += __shfl_xor_sync(0xffffffffu, s, o);
        q += __shfl_xor_sync(0xffffffffu, q, o);
    }
    if ((tid & 31) == 0) { rs[tid >> 5] = s; rq[tid >> 5] = q; }
    __syncthreads();
    s = rs[0]; q = rq[0];
#pragma unroll
    for (int i = 1; i < 8; i++) { s += rs[i]; q += rq[i]; }
    const float mean = s * (1.f / DM);
    const float var  = q * (1.f / DM) - mean * mean;
    const float inv  = rsqrtf(var + 1e-5f);
    float4 gg = ((const float4*)gamma)[tid];
    float4 bb = ((const float4*)beta)[tid];
    float4 o;
    o.x = (x0 - mean) * inv * gg.x + bb.x;
    o.y = (x1 - mean) * inv * gg.y + bb.y;
    o.z = (x2 - mean) * inv * gg.z + bb.z;
    o.w = (x3 - mean) * inv * gg.w + bb.w;
    ((float4*)(X + (size_t)r * DM))[tid] = o;
}

// ======================= launch =======================
extern "C" void kernel_launch(void* const* d_in, const int* in_sizes, int n_in,
                              void* d_out, int out_size)
{
    (void)in_sizes; (void)n_in; (void)out_size;
    const float* E     = (const float*)d_in[0];
    const float* Wq    = (const float*)d_in[1];
    const float* bq    = (const float*)d_in[2];
    const float* Wk    = (const float*)d_in[3];
    const float* bk    = (const float*)d_in[4];
    const float* Wv    = (const float*)d_in[5];
    const float* bv    = (const float*)d_in[6];
    const float* gamma = (const float*)d_in[7];
    const float* beta  = (const float*)d_in[8];
    const float* W1    = (const float*)d_in[9];
    const float* b1    = (const float*)d_in[10];
    const float* W2    = (const float*)d_in[11];
    const float* b2    = (const float*)d_in[12];
    float* out = (float*)d_out;

    float *Q, *K, *V, *S, *AE, *X, *H, *Wqt, *Wkt, *Wvt, *W1t, *W2t, *Vt;
    cudaGetSymbolAddress((void**)&Q,   g_Q);
    cudaGetSymbolAddress((void**)&K,   g_K);
    cudaGetSymbolAddress((void**)&V,   g_V);
    cudaGetSymbolAddress((void**)&S,   g_S);
    cudaGetSymbolAddress((void**)&AE,  g_AE);
    cudaGetSymbolAddress((void**)&X,   g_X);
    cudaGetSymbolAddress((void**)&H,   g_H);
    cudaGetSymbolAddress((void**)&Wqt, g_Wqt);
    cudaGetSymbolAddress((void**)&Wkt, g_Wkt);
    cudaGetSymbolAddress((void**)&Wvt, g_Wvt);
    cudaGetSymbolAddress((void**)&W1t, g_W1t);
    cudaGetSymbolAddress((void**)&W2t, g_W2t);
    cudaGetSymbolAddress((void**)&Vt,  g_Vt);

    dim3 tb(32, 8);
    transpose_k<<<dim3(DM / 32, DM / 32), tb>>>(Wq, Wqt, DM, DM);
    transpose_k<<<dim3(DM / 32, DM / 32), tb>>>(Wk, Wkt, DM, DM);
    transpose_k<<<dim3(DM / 32, DM / 32), tb>>>(Wv, Wvt, DM, DM);
    transpose_k<<<dim3(DF / 32, DM / 32), tb>>>(W1, W1t, DM, DF);
    transpose_k<<<dim3(DM / 32, DF / 32), tb>>>(W2, W2t, DF, DM);

    dim3 blk(128);
    dim3 gProj(DM / 128, NT / 128);   // 8 x 32
    dim3 gS(NT / 128, NT / 128);      // 32 x 32
    dim3 gF1(DF / 128, NT / 128);     // 32 x 32

    // QKV projections
    tc_gemm<false, false, false, true><<<gProj, blk>>>(E, Wqt, bq, Q, DM, DM, 1.f);
    tc_gemm<false, false, false, true><<<gProj, blk>>>(E, Wkt, bk, K, DM, DM, 1.f);
    tc_gemm<false, false, false, true><<<gProj, blk>>>(E, Wvt, bv, V, DM, DM, 1.f);

    // S = Q @ K^T / 32 (lower-triangle blocks only)
    tc_gemm<true, false, false, false><<<gS, blk>>>(Q, K, nullptr, S, NT, DM, 0.03125f);

    softmax_causal<<<NT, 256>>>(S);

    // AE = A @ V (B operand = V^T, triangular K)
    transpose_k<<<dim3(DM / 32, NT / 32), tb>>>(V, Vt, NT, DM);
    tc_gemm<false, true, false, false><<<gProj, blk>>>(S, Vt, nullptr, AE, DM, NT, 1.f);

    add_layernorm<<<NT, 256>>>(AE, E, gamma, beta, X);

    // FFN
    tc_gemm<false, false, true, true><<<gF1, blk>>>(X, W1t, b1, H, DF, DM, 1.f);
    tc_gemm<false, false, false, true><<<gProj, blk>>>(H, W2t, b2, out, DM, DF, 1.f);
}

// round 5
// speedup vs baseline: 2.2104x; 1.1592x over previous
#include <cuda_runtime.h>
#include <cuda_fp16.h>
#include <cstdint>

#define NT 4096   // tokens
#define DM 1024   // model dim
#define DF 4096   // ffn dim

// ---- scratch (static device globals; allowed) ----
__device__ float g_QKV[(size_t)NT * 3072];        // fused Q|K|V, row stride 3072
__device__ float g_S[(size_t)NT * NT];
__device__ float g_AE[NT * DM];
__device__ float g_X[NT * DM];
__device__ float g_H[(size_t)NT * DF];
__device__ float g_Wqkvt[3072 * DM];              // [3072][1024] transposed weights
__device__ float g_W1t[(size_t)DM * DF];          // [4096][1024]
__device__ float g_W2t[(size_t)DM * DF];          // [1024][4096]
__device__ float g_Vt[(size_t)NT * DM];           // [1024][4096]
__device__ float g_bqkv[3072];

__device__ __forceinline__ uint32_t h2pack(float lo, float hi) {
    __half2 h = __floats2half2_rn(lo, hi);
    return *(uint32_t*)&h;
}
__device__ __forceinline__ uint32_t smem_u32(const void* p) {
    uint32_t a;
    asm("{ .reg .u64 t; cvta.to.shared.u64 t, %1; cvt.u32.u64 %0, t; }" : "=r"(a) : "l"(p));
    return a;
}
__device__ __forceinline__ void mma_f16(float* c, const uint32_t* a, const uint32_t* b) {
    asm volatile(
        "mma.sync.aligned.m16n8k16.row.col.f32.f16.f16.f32 "
        "{%0,%1,%2,%3}, {%4,%5,%6,%7}, {%8,%9}, {%0,%1,%2,%3};"
        : "+f"(c[0]), "+f"(c[1]), "+f"(c[2]), "+f"(c[3])
        : "r"(a[0]), "r"(a[1]), "r"(a[2]), "r"(a[3]), "r"(b[0]), "r"(b[1]));
}
__device__ __forceinline__ void ldsm4(uint32_t& r0, uint32_t& r1, uint32_t& r2, uint32_t& r3,
                                      uint32_t addr) {
    asm volatile("ldmatrix.sync.aligned.m8n8.x4.shared.b16 {%0,%1,%2,%3}, [%4];"
                 : "=r"(r0), "=r"(r1), "=r"(r2), "=r"(r3) : "r"(addr));
}

// ===========================================================================
// fp16 mma.sync GEMM.  C[M,N] = alpha * A[M,K] @ Bt[N,K]^T (+bias) (+relu)
// fp32 in gmem, converted to fp16 at STS. Tiles 128x128x16, 128 threads
// (4 warps 2x2 -> 64x64 warp tiles). Smem rows = 16 fp16 = 32B = 2 chunks,
// swizzle c_phys = c ^ ((row>>2)&1): bank-bijective for STS.128 & ldmatrix.
// ===========================================================================
template <bool CAUSAL, bool TRIK, bool RELU, bool BIAS>
__global__ __launch_bounds__(128, 2)
void hgemm(const float* __restrict__ A, const float* __restrict__ Bt,
           const float* __restrict__ bias, float* __restrict__ C,
           int N, int Kdim, int lda, int ldb, float alpha)
{
    __shared__ __align__(16) uint32_t As[2][1024];   // 2 bufs x 128 rows x 8 words
    __shared__ __align__(16) uint32_t Bs[2][1024];

    const int bx = blockIdx.x, by = blockIdx.y;
    if (CAUSAL && bx > by) return;

    const int tid  = threadIdx.x;
    const int wid  = tid >> 5;
    const int lane = tid & 31;
    const int g    = lane >> 2;
    const int tig  = lane & 3;
    const int l7   = lane & 7;
    const int q    = lane >> 3;          // ldmatrix matrix index

    const int wmt = (wid >> 1) * 4;      // first m16-tile of warp
    const int wnt = (wid & 1) * 8;       // first n8-tile of warp

    int kEnd = Kdim;
    if (TRIK) { int lim = (by + 1) * 128; kEnd = lim < Kdim ? lim : Kdim; }
    const int niter = kEnd >> 4;

    const float* aptr = A  + (size_t)(by * 128 + tid) * (size_t)lda;
    const float* bptr = Bt + (size_t)(bx * 128 + tid) * (size_t)ldb;

    const uint32_t aSm = smem_u32(As);
    const uint32_t bSm = smem_u32(Bs);
    const int swt = (tid >> 2) & 1;      // store-side row swizzle

    // precomputed ldmatrix lane addresses (buffer offset added per iter)
    uint32_t addrA[4], addrB[4];
#pragma unroll
    for (int m = 0; m < 4; m++) {
        int r = (wmt + m) * 16 + (q & 1) * 8 + l7;
        addrA[m] = aSm + (uint32_t)r * 32u + (uint32_t)((((q >> 1) ^ ((r >> 2) & 1))) << 4);
    }
#pragma unroll
    for (int p = 0; p < 4; p++) {
        int r = (wnt + 2 * p + (q >> 1)) * 8 + l7;
        addrB[p] = bSm + (uint32_t)r * 32u + (uint32_t)((((q & 1) ^ ((r >> 2) & 1))) << 4);
    }

    float acc[4][8][4];
#pragma unroll
    for (int i = 0; i < 4; i++)
#pragma unroll
        for (int j = 0; j < 8; j++)
#pragma unroll
            for (int t = 0; t < 4; t++) acc[i][j][t] = 0.f;

    float4 ra[4], rb[4];

#define LDG_T(k0) do { \
        _Pragma("unroll") \
        for (int t = 0; t < 4; t++) { \
            ra[t] = *(const float4*)(aptr + (k0) + t * 4); \
            rb[t] = *(const float4*)(bptr + (k0) + t * 4); \
        } } while (0)

#define STS_T(buf) do { \
        _Pragma("unroll") \
        for (int c = 0; c < 2; c++) { \
            uint4 wa, wb; \
            wa.x = h2pack(ra[2*c].x,   ra[2*c].y);   wa.y = h2pack(ra[2*c].z,   ra[2*c].w); \
            wa.z = h2pack(ra[2*c+1].x, ra[2*c+1].y); wa.w = h2pack(ra[2*c+1].z, ra[2*c+1].w); \
            wb.x = h2pack(rb[2*c].x,   rb[2*c].y);   wb.y = h2pack(rb[2*c].z,   rb[2*c].w); \
            wb.z = h2pack(rb[2*c+1].x, rb[2*c+1].y); wb.w = h2pack(rb[2*c+1].z, rb[2*c+1].w); \
            const int wi = tid * 8 + ((c ^ swt) << 2); \
            *(uint4*)&As[buf][wi] = wa; \
            *(uint4*)&Bs[buf][wi] = wb; \
        } } while (0)

    LDG_T(0);
    STS_T(0);
    __syncthreads();

    for (int i = 0; i < niter; i++) {
        const int b = i & 1;
        if (i + 1 < niter) LDG_T((i + 1) * 16);

        const uint32_t bo = (uint32_t)b * 4096u;
        uint32_t af[4][4], bf[8][2];
#pragma unroll
        for (int m = 0; m < 4; m++)
            ldsm4(af[m][0], af[m][1], af[m][2], af[m][3], addrA[m] + bo);
#pragma unroll
        for (int p = 0; p < 4; p++)
            ldsm4(bf[2 * p][0], bf[2 * p][1], bf[2 * p + 1][0], bf[2 * p + 1][1],
                  addrB[p] + bo);
#pragma unroll
        for (int m = 0; m < 4; m++)
#pragma unroll
            for (int n = 0; n < 8; n++)
                mma_f16(acc[m][n], af[m], bf[n]);

        if (i + 1 < niter) STS_T(b ^ 1);
        __syncthreads();
    }

    // ---- epilogue: direct float2 stores ----
    const int rowBase = by * 128 + (wid >> 1) * 64 + g;
    const int colBase = bx * 128 + (wid & 1) * 64 + tig * 2;
#pragma unroll
    for (int m = 0; m < 4; m++) {
        const int r0 = rowBase + m * 16;
#pragma unroll
        for (int n = 0; n < 8; n++) {
            const int col = colBase + n * 8;
            float b0 = 0.f, b1 = 0.f;
            if (BIAS) { b0 = bias[col]; b1 = bias[col + 1]; }
            float2 v0, v1;
            v0.x = acc[m][n][0] * alpha + b0;
            v0.y = acc[m][n][1] * alpha + b1;
            v1.x = acc[m][n][2] * alpha + b0;
            v1.y = acc[m][n][3] * alpha + b1;
            if (RELU) {
                v0.x = fmaxf(v0.x, 0.f); v0.y = fmaxf(v0.y, 0.f);
                v1.x = fmaxf(v1.x, 0.f); v1.y = fmaxf(v1.y, 0.f);
            }
            *(float2*)(C + (size_t)r0 * N + col)       = v0;
            *(float2*)(C + (size_t)(r0 + 8) * N + col) = v1;
        }
    }
#undef LDG_T
#undef STS_T
}

// ============ transpose with strides: out[c][r] = in[r][c] ============
__global__ void transpose_k(const float* __restrict__ in, float* __restrict__ out,
                            int inS, int outS)
{
    __shared__ float t[32][33];
    const int bc = blockIdx.x * 32;
    const int br = blockIdx.y * 32;
    const int x = threadIdx.x, y = threadIdx.y;
#pragma unroll
    for (int j = 0; j < 32; j += 8)
        t[y + j][x] = in[(size_t)(br + y + j) * inS + bc + x];
    __syncthreads();
#pragma unroll
    for (int j = 0; j < 32; j += 8)
        out[(size_t)(bc + y + j) * outS + br + x] = t[x][y + j];
}

// ============ fast exp (FMA pipe) ============
__device__ __forceinline__ float fast_exp(float x) {
    float y = x * 1.4426950408889634f;
    float n = rintf(y);
    float f = y - n;
    float p = 1.5403530393e-4f;
    p = fmaf(p, f, 1.3333558146e-3f);
    p = fmaf(p, f, 9.6181291076e-3f);
    p = fmaf(p, f, 5.5504108665e-2f);
    p = fmaf(p, f, 2.4022650696e-1f);
    p = fmaf(p, f, 6.9314718056e-1f);
    p = fmaf(p, f, 1.0f);
    float ec = fmaxf(n, -126.f);
    return __int_as_float(((int)ec + 127) << 23) * p;
}

// ============ causal softmax ============
__global__ void softmax_causal(float* __restrict__ S)
{
    const int r = blockIdx.x;
    const int tid = threadIdx.x;
    const int limit = ((r >> 7) + 1) << 7;
    float* row = S + (size_t)r * NT;

    float vals[16];
    int n = 0;
    float m = -1e30f;
    for (int j = tid; j < limit; j += 256) {
        float v = (j <= r) ? row[j] : -1e30f;
        vals[n++] = v;
        m = fmaxf(m, v);
    }
    __shared__ float redm[8], reds[8];
#pragma unroll
    for (int o = 16; o > 0; o >>= 1) m = fmaxf(m, __shfl_xor_sync(0xffffffffu, m, o));
    if ((tid & 31) == 0) redm[tid >> 5] = m;
    __syncthreads();
    m = redm[0];
#pragma unroll
    for (int i = 1; i < 8; i++) m = fmaxf(m, redm[i]);

    float s = 0.f;
    for (int i = 0; i < n; i++) { float e = fast_exp(vals[i] - m); vals[i] = e; s += e; }
#pragma unroll
    for (int o = 16; o > 0; o >>= 1) s += __shfl_xor_sync(0xffffffffu, s, o);
    if ((tid & 31) == 0) reds[tid >> 5] = s;
    __syncthreads();
    s = reds[0];
#pragma unroll
    for (int i = 1; i < 8; i++) s += reds[i];

    const float inv = 1.f / s;
    n = 0;
    for (int j = tid; j < limit; j += 256) row[j] = vals[n++] * inv;
}

// ============ add + LayerNorm ============
__global__ void add_layernorm(const float* __restrict__ AE, const float* __restrict__ E,
                              const float* __restrict__ gamma, const float* __restrict__ beta,
                              float* __restrict__ X)
{
    const int r = blockIdx.x;
    const int tid = threadIdx.x;
    float4 a = ((const float4*)(AE + (size_t)r * DM))[tid];
    float4 e = ((const float4*)(E + (size_t)r * DM))[tid];
    float x0 = a.x + e.x, x1 = a.y + e.y, x2 = a.z + e.z, x3 = a.w + e.w;
    float s = x0 + x1 + x2 + x3;
    float q = x0 * x0 + x1 * x1 + x2 * x2 + x3 * x3;
    __shared__ float rs[8], rq[8];
#pragma unroll
    for (int o = 16; o > 0; o >>= 1) {
        s += __shfl_xor_sync(0xffffffffu, s, o);
        q += __shfl_xor_sync(0xffffffffu, q, o);
    }
    if ((tid & 31) == 0) { rs[tid >> 5] = s; rq[tid >> 5] = q; }
    __syncthreads();
    s = rs[0]; q = rq[0];
#pragma unroll
    for (int i = 1; i < 8; i++) { s += rs[i]; q += rq[i]; }
    const float mean = s * (1.f / DM);
    const float var  = q * (1.f / DM) - mean * mean;
    const float inv  = rsqrtf(var + 1e-5f);
    float4 gg = ((const float4*)gamma)[tid];
    float4 bb = ((const float4*)beta)[tid];
    float4 o;
    o.x = (x0 - mean) * inv * gg.x + bb.x;
    o.y = (x1 - mean) * inv * gg.y + bb.y;
    o.z = (x2 - mean) * inv * gg.z + bb.z;
    o.w = (x3 - mean) * inv * gg.w + bb.w;
    ((float4*)(X + (size_t)r * DM))[tid] = o;
}

// ============ launch ============
extern "C" void kernel_launch(void* const* d_in, const int* in_sizes, int n_in,
                              void* d_out, int out_size)
{
    (void)in_sizes; (void)n_in; (void)out_size;
    const float* E     = (const float*)d_in[0];
    const float* Wq    = (const float*)d_in[1];
    const float* bq    = (const float*)d_in[2];
    const float* Wk    = (const float*)d_in[3];
    const float* bk    = (const float*)d_in[4];
    const float* Wv    = (const float*)d_in[5];
    const float* bv    = (const float*)d_in[6];
    const float* gamma = (const float*)d_in[7];
    const float* beta  = (const float*)d_in[8];
    const float* W1    = (const float*)d_in[9];
    const float* b1    = (const float*)d_in[10];
    const float* W2    = (const float*)d_in[11];
    const float* b2    = (const float*)d_in[12];
    float* out = (float*)d_out;

    float *QKV, *S, *AE, *X, *H, *Wqkvt, *W1t, *W2t, *Vt, *bqkv;
    cudaGetSymbolAddress((void**)&QKV,   g_QKV);
    cudaGetSymbolAddress((void**)&S,     g_S);
    cudaGetSymbolAddress((void**)&AE,    g_AE);
    cudaGetSymbolAddress((void**)&X,     g_X);
    cudaGetSymbolAddress((void**)&H,     g_H);
    cudaGetSymbolAddress((void**)&Wqkvt, g_Wqkvt);
    cudaGetSymbolAddress((void**)&W1t,   g_W1t);
    cudaGetSymbolAddress((void**)&W2t,   g_W2t);
    cudaGetSymbolAddress((void**)&Vt,    g_Vt);
    cudaGetSymbolAddress((void**)&bqkv,  g_bqkv);

    dim3 tb(32, 8);
    // weight transposes into fused buffer  (out[c][r] = in[r][c])
    transpose_k<<<dim3(DM / 32, DM / 32), tb>>>(Wq, Wqkvt,                  DM, DM);
    transpose_k<<<dim3(DM / 32, DM / 32), tb>>>(Wk, Wqkvt + 1024 * DM,      DM, DM);
    transpose_k<<<dim3(DM / 32, DM / 32), tb>>>(Wv, Wqkvt + 2048 * DM,      DM, DM);
    transpose_k<<<dim3(DF / 32, DM / 32), tb>>>(W1, W1t,                    DF, DM);
    transpose_k<<<dim3(DM / 32, DF / 32), tb>>>(W2, W2t,                    DM, DF);
    cudaMemcpyAsync(bqkv,        bq, DM * sizeof(float), cudaMemcpyDeviceToDevice);
    cudaMemcpyAsync(bqkv + 1024, bk, DM * sizeof(float), cudaMemcpyDeviceToDevice);
    cudaMemcpyAsync(bqkv + 2048, bv, DM * sizeof(float), cudaMemcpyDeviceToDevice);

    dim3 blk(128);

    // fused QKV projection: [4096,3072]
    hgemm<false, false, false, true><<<dim3(3072 / 128, NT / 128), blk>>>(
        E, Wqkvt, bqkv, QKV, 3072, DM, DM, DM, 1.f);

    // S = Q @ K^T / 32 (lower-triangle blocks only)
    hgemm<true, false, false, false><<<dim3(NT / 128, NT / 128), blk>>>(
        QKV, QKV + 1024, nullptr, S, NT, DM, 3072, 3072, 0.03125f);

    softmax_causal<<<NT, 256>>>(S);

    // Vt[d][t] = V[t][d]
    transpose_k<<<dim3(DM / 32, NT / 32), tb>>>(QKV + 2048, Vt, 3072, NT);

    // AE = A @ V (triangular K)
    hgemm<false, true, false, false><<<dim3(DM / 128, NT / 128), blk>>>(
        S, Vt, nullptr, AE, DM, NT, NT, NT, 1.f);

    add_layernorm<<<NT, 256>>>(AE, E, gamma, beta, X);

    // FFN
    hgemm<false, false, true, true><<<dim3(DF / 128, NT / 128), blk>>>(
        X, W1t, b1, H, DF, DM, DM, DM, 1.f);
    hgemm<false, false, false, true><<<dim3(DM / 128, NT / 128), blk>>>(
        H, W2t, b2, out, DM, DF, DF, DF, 1.f);
}

// round 8
// speedup vs baseline: 5.8449x; 2.6443x over previous
#include <cuda_runtime.h>
#include <cuda_fp16.h>
#include <cstdint>

#define NT 4096   // tokens
#define DM 1024   // model dim
#define DF 4096   // ffn dim

// ---- scratch (static device globals; allowed) ----
__device__ __half g_Eh[(size_t)NT * DM];
__device__ __half g_QKVh[(size_t)NT * 3072];      // fused Q|K|V (half), stride 3072
__device__ float  g_S[(size_t)NT * NT];           // attention scores fp32
__device__ __half g_Sh[(size_t)NT * NT];          // softmax probs half
__device__ float  g_AE[NT * DM];
__device__ __half g_Xh[NT * DM];
__device__ __half g_Hh[(size_t)NT * DF];
__device__ __half g_Wqkvth[3072 * DM];            // [3072][1024] W^T half
__device__ __half g_W1th[(size_t)DF * DM];        // [4096][1024]
__device__ __half g_W2th[(size_t)DM * DF];        // [1024][4096]
__device__ __half g_Vth[(size_t)DM * NT];         // [1024][4096] V^T half
__device__ float  g_bqkv[3072];

__device__ __forceinline__ uint32_t smem_u32(const void* p) {
    uint32_t a;
    asm("{ .reg .u64 t; cvta.to.shared.u64 t, %1; cvt.u32.u64 %0, t; }" : "=r"(a) : "l"(p));
    return a;
}
__device__ __forceinline__ void mma_f16(float* c, const uint32_t* a, const uint32_t* b) {
    asm volatile(
        "mma.sync.aligned.m16n8k16.row.col.f32.f16.f16.f32 "
        "{%0,%1,%2,%3}, {%4,%5,%6,%7}, {%8,%9}, {%0,%1,%2,%3};"
        : "+f"(c[0]), "+f"(c[1]), "+f"(c[2]), "+f"(c[3])
        : "r"(a[0]), "r"(a[1]), "r"(a[2]), "r"(a[3]), "r"(b[0]), "r"(b[1]));
}
__device__ __forceinline__ void ldsm4(uint32_t& r0, uint32_t& r1, uint32_t& r2, uint32_t& r3,
                                      uint32_t addr) {
    asm volatile("ldmatrix.sync.aligned.m8n8.x4.shared.b16 {%0,%1,%2,%3}, [%4];"
                 : "=r"(r0), "=r"(r1), "=r"(r2), "=r"(r3) : "r"(addr));
}

// ===========================================================================
// fp16 mma.sync GEMM, synchronous LDG->STS double buffer (proven R5 pipeline,
// widened).  C[M,N] = alpha * A[M,K] @ Bt[N,K]^T (+bias) (+relu); A,Bt half.
// Tiles 128x128x32, 256 threads = 8 warps (2 m-slabs x 4 n-slabs, 64x32 each).
// Smem tile row = 32 half = 64B = 4 chunks; swizzle c_phys = c ^ ((r>>1)&3)
//   -> bank-bijective for STS.128 and ldmatrix (verified by enumeration).
// ===========================================================================
template <bool CAUSAL, bool TRIK, bool RELU, bool BIAS, bool HALF_OUT>
__global__ __launch_bounds__(256, 2)
void hgemm2(const __half* __restrict__ A, const __half* __restrict__ Bt,
            const float* __restrict__ bias, void* __restrict__ Cv,
            int N, int Kdim, int lda, int ldb, float alpha)
{
    __shared__ __align__(16) uint32_t As[2][2048];   // 2 bufs x 128 rows x 16 words
    __shared__ __align__(16) uint32_t Bs[2][2048];

    const int bx = blockIdx.x, by = blockIdx.y;
    if (CAUSAL && bx > by) return;

    const int tid  = threadIdx.x;
    const int wid  = tid >> 5;
    const int lane = tid & 31;
    const int g    = lane >> 2;
    const int tig  = lane & 3;
    const int l7   = lane & 7;
    const int q    = lane >> 3;

    const int wmt = (wid & 1) * 4;        // first m16-tile (2 slabs of 64)
    const int wnt = (wid >> 1) * 4;       // first n8-tile  (4 slabs of 32)

    int kEnd = Kdim;
    if (TRIK) { int lim = (by + 1) * 128; kEnd = lim < Kdim ? lim : Kdim; }
    const int niter = kEnd >> 5;

    // copy side: 512 16B-chunks per operand tile, 2 per thread
    const int r0c = tid >> 2, c0c = tid & 3;          // chunk set 0: rows 0..63
    const int w0 = r0c * 16 + ((c0c ^ ((r0c >> 1) & 3)) << 2);
    const int r1c = r0c + 64;
    const int w1 = r1c * 16 + ((c0c ^ ((r1c >> 1) & 3)) << 2);
    const __half* aG0 = A  + (size_t)(by * 128 + r0c) * (size_t)lda + c0c * 8;
    const __half* aG1 = A  + (size_t)(by * 128 + r1c) * (size_t)lda + c0c * 8;
    const __half* bG0 = Bt + (size_t)(bx * 128 + r0c) * (size_t)ldb + c0c * 8;
    const __half* bG1 = Bt + (size_t)(bx * 128 + r1c) * (size_t)ldb + c0c * 8;

    uint4 ra0, ra1, rb0, rb1;
#define LDG_T(k0) do { \
        ra0 = *(const uint4*)(aG0 + (k0)); \
        ra1 = *(const uint4*)(aG1 + (k0)); \
        rb0 = *(const uint4*)(bG0 + (k0)); \
        rb1 = *(const uint4*)(bG1 + (k0)); \
    } while (0)
#define STS_T(buf) do { \
        *(uint4*)&As[buf][w0] = ra0; \
        *(uint4*)&As[buf][w1] = ra1; \
        *(uint4*)&Bs[buf][w0] = rb0; \
        *(uint4*)&Bs[buf][w1] = rb1; \
    } while (0)

    const uint32_t aSm = smem_u32(As);
    const uint32_t bSm = smem_u32(Bs);

    // ldmatrix lane byte-offsets (relative to buffer base)
    uint32_t aOff[4][2], bOff[2][2];
#pragma unroll
    for (int m = 0; m < 4; m++) {
        int r = (wmt + m) * 16 + (q & 1) * 8 + l7;
#pragma unroll
        for (int ks = 0; ks < 2; ks++) {
            uint32_t c = (uint32_t)(2 * ks) + (uint32_t)(q >> 1);
            aOff[m][ks] = (uint32_t)r * 64u + ((c ^ ((uint32_t)(r >> 1) & 3u)) << 4);
        }
    }
#pragma unroll
    for (int p = 0; p < 2; p++) {
        int r = (wnt + 2 * p + (q >> 1)) * 8 + l7;
#pragma unroll
        for (int ks = 0; ks < 2; ks++) {
            uint32_t c = (uint32_t)(2 * ks) + (uint32_t)(q & 1);
            bOff[p][ks] = (uint32_t)r * 64u + ((c ^ ((uint32_t)(r >> 1) & 3u)) << 4);
        }
    }

    float acc[4][4][4];
#pragma unroll
    for (int i = 0; i < 4; i++)
#pragma unroll
        for (int j = 0; j < 4; j++)
#pragma unroll
            for (int t = 0; t < 4; t++) acc[i][j][t] = 0.f;

    LDG_T(0);
    STS_T(0);
    __syncthreads();

    for (int i = 0; i < niter; i++) {
        const int b = i & 1;
        if (i + 1 < niter) LDG_T((i + 1) * 32);

        const uint32_t aBase = aSm + (uint32_t)b * 8192u;
        const uint32_t bBase = bSm + (uint32_t)b * 8192u;
#pragma unroll
        for (int ks = 0; ks < 2; ks++) {
            uint32_t af[4][4], bf[4][2];
#pragma unroll
            for (int m = 0; m < 4; m++)
                ldsm4(af[m][0], af[m][1], af[m][2], af[m][3], aBase + aOff[m][ks]);
#pragma unroll
            for (int p = 0; p < 2; p++)
                ldsm4(bf[2 * p][0], bf[2 * p][1], bf[2 * p + 1][0], bf[2 * p + 1][1],
                      bBase + bOff[p][ks]);
#pragma unroll
            for (int m = 0; m < 4; m++)
#pragma unroll
                for (int n = 0; n < 4; n++)
                    mma_f16(acc[m][n], af[m], bf[n]);
        }

        if (i + 1 < niter) STS_T(b ^ 1);
        __syncthreads();
    }

    // ---- epilogue ----
    const int rowBase = by * 128 + (wid & 1) * 64 + g;
    const int colBase = bx * 128 + (wid >> 1) * 32 + tig * 2;
#pragma unroll
    for (int m = 0; m < 4; m++) {
        const int r0 = rowBase + m * 16;
#pragma unroll
        for (int n = 0; n < 4; n++) {
            const int col = colBase + n * 8;
            float b0 = 0.f, b1 = 0.f;
            if (BIAS) { b0 = bias[col]; b1 = bias[col + 1]; }
            float v0x = acc[m][n][0] * alpha + b0;
            float v0y = acc[m][n][1] * alpha + b1;
            float v1x = acc[m][n][2] * alpha + b0;
            float v1y = acc[m][n][3] * alpha + b1;
            if (RELU) {
                v0x = fmaxf(v0x, 0.f); v0y = fmaxf(v0y, 0.f);
                v1x = fmaxf(v1x, 0.f); v1y = fmaxf(v1y, 0.f);
            }
            if (HALF_OUT) {
                __half* C = (__half*)Cv;
                *(__half2*)(C + (size_t)r0 * N + col)       = __floats2half2_rn(v0x, v0y);
                *(__half2*)(C + (size_t)(r0 + 8) * N + col) = __floats2half2_rn(v1x, v1y);
            } else {
                float* C = (float*)Cv;
                *(float2*)(C + (size_t)r0 * N + col)       = make_float2(v0x, v0y);
                *(float2*)(C + (size_t)(r0 + 8) * N + col) = make_float2(v1x, v1y);
            }
        }
    }
#undef LDG_T
#undef STS_T
}

// ============ fp32 -> fp16 convert ============
__global__ void f2h(const float* __restrict__ in, __half* __restrict__ out, int n4)
{
    int i = blockIdx.x * blockDim.x + threadIdx.x;
    if (i < n4) {
        float4 v = ((const float4*)in)[i];
        ((__half2*)out)[i * 2]     = __floats2half2_rn(v.x, v.y);
        ((__half2*)out)[i * 2 + 1] = __floats2half2_rn(v.z, v.w);
    }
}

// ============ transpose fp32 -> fp16: out[c][r] = in[r][c] ============
__global__ void transpose_f2h(const float* __restrict__ in, __half* __restrict__ out,
                              int inS, int outS)
{
    __shared__ float t[32][33];
    const int bc = blockIdx.x * 32;
    const int br = blockIdx.y * 32;
    const int x = threadIdx.x, y = threadIdx.y;
#pragma unroll
    for (int j = 0; j < 32; j += 8)
        t[y + j][x] = in[(size_t)(br + y + j) * inS + bc + x];
    __syncthreads();
#pragma unroll
    for (int j = 0; j < 32; j += 8)
        out[(size_t)(bc + y + j) * outS + br + x] = __float2half(t[x][y + j]);
}

// ============ transpose fp16 -> fp16 ============
__global__ void transpose_h2h(const __half* __restrict__ in, __half* __restrict__ out,
                              int inS, int outS)
{
    __shared__ __half t[32][34];
    const int bc = blockIdx.x * 32;
    const int br = blockIdx.y * 32;
    const int x = threadIdx.x, y = threadIdx.y;
#pragma unroll
    for (int j = 0; j < 32; j += 8)
        t[y + j][x] = in[(size_t)(br + y + j) * inS + bc + x];
    __syncthreads();
#pragma unroll
    for (int j = 0; j < 32; j += 8)
        out[(size_t)(bc + y + j) * outS + br + x] = t[x][y + j];
}

// ============ fast exp (FMA pipe) ============
__device__ __forceinline__ float fast_exp(float x) {
    float y = x * 1.4426950408889634f;
    float n = rintf(y);
    float f = y - n;
    float p = 1.5403530393e-4f;
    p = fmaf(p, f, 1.3333558146e-3f);
    p = fmaf(p, f, 9.6181291076e-3f);
    p = fmaf(p, f, 5.5504108665e-2f);
    p = fmaf(p, f, 2.4022650696e-1f);
    p = fmaf(p, f, 6.9314718056e-1f);
    p = fmaf(p, f, 1.0f);
    float ec = fmaxf(n, -126.f);
    return __int_as_float(((int)ec + 127) << 23) * p;
}

// ============ causal softmax: fp32 scores -> fp16 probs (zero-padded) ============
__global__ void softmax_causal(const float* __restrict__ S, __half* __restrict__ Sh)
{
    const int r = blockIdx.x;
    const int tid = threadIdx.x;
    const int limit = ((r >> 7) + 1) << 7;
    const float* row = S + (size_t)r * NT;
    __half* rowh = Sh + (size_t)r * NT;

    float vals[16];
    int n = 0;
    float m = -1e30f;
    for (int j = tid; j < limit; j += 256) {
        float v = (j <= r) ? row[j] : -1e30f;
        vals[n++] = v;
        m = fmaxf(m, v);
    }
    __shared__ float redm[8], reds[8];
#pragma unroll
    for (int o = 16; o > 0; o >>= 1) m = fmaxf(m, __shfl_xor_sync(0xffffffffu, m, o));
    if ((tid & 31) == 0) redm[tid >> 5] = m;
    __syncthreads();
    m = redm[0];
#pragma unroll
    for (int i = 1; i < 8; i++) m = fmaxf(m, redm[i]);

    float s = 0.f;
    for (int i = 0; i < n; i++) { float e = fast_exp(vals[i] - m); vals[i] = e; s += e; }
#pragma unroll
    for (int o = 16; o > 0; o >>= 1) s += __shfl_xor_sync(0xffffffffu, s, o);
    if ((tid & 31) == 0) reds[tid >> 5] = s;
    __syncthreads();
    s = reds[0];
#pragma unroll
    for (int i = 1; i < 8; i++) s += reds[i];

    const float inv = 1.f / s;
    n = 0;
    for (int j = tid; j < limit; j += 256) rowh[j] = __float2half(vals[n++] * inv);
}

// ============ add + LayerNorm -> fp16 X ============
__global__ void add_layernorm(const float* __restrict__ AE, const float* __restrict__ E,
                              const float* __restrict__ gamma, const float* __restrict__ beta,
                              __half* __restrict__ X)
{
    const int r = blockIdx.x;
    const int tid = threadIdx.x;
    float4 a = ((const float4*)(AE + (size_t)r * DM))[tid];
    float4 e = ((const float4*)(E + (size_t)r * DM))[tid];
    float x0 = a.x + e.x, x1 = a.y + e.y, x2 = a.z + e.z, x3 = a.w + e.w;
    float s = x0 + x1 + x2 + x3;
    float q = x0 * x0 + x1 * x1 + x2 * x2 + x3 * x3;
    __shared__ float rs[8], rq[8];
#pragma unroll
    for (int o = 16; o > 0; o >>= 1) {
        s += __shfl_xor_sync(0xffffffffu, s, o);
        q += __shfl_xor_sync(0xffffffffu, q, o);
    }
    if ((tid & 31) == 0) { rs[tid >> 5] = s; rq[tid >> 5] = q; }
    __syncthreads();
    s = rs[0]; q = rq[0];
#pragma unroll
    for (int i = 1; i < 8; i++) { s += rs[i]; q += rq[i]; }
    const float mean = s * (1.f / DM);
    const float var  = q * (1.f / DM) - mean * mean;
    const float inv  = rsqrtf(var + 1e-5f);
    float4 gg = ((const float4*)gamma)[tid];
    float4 bb = ((const float4*)beta)[tid];
    __half2 o0 = __floats2half2_rn((x0 - mean) * inv * gg.x + bb.x,
                                   (x1 - mean) * inv * gg.y + bb.y);
    __half2 o1 = __floats2half2_rn((x2 - mean) * inv * gg.z + bb.z,
                                   (x3 - mean) * inv * gg.w + bb.w);
    ((__half2*)(X + (size_t)r * DM))[tid * 2]     = o0;
    ((__half2*)(X + (size_t)r * DM))[tid * 2 + 1] = o1;
}

// ============ launch ============
extern "C" void kernel_launch(void* const* d_in, const int* in_sizes, int n_in,
                              void* d_out, int out_size)
{
    (void)in_sizes; (void)n_in; (void)out_size;
    const float* E     = (const float*)d_in[0];
    const float* Wq    = (const float*)d_in[1];
    const float* bq    = (const float*)d_in[2];
    const float* Wk    = (const float*)d_in[3];
    const float* bk    = (const float*)d_in[4];
    const float* Wv    = (const float*)d_in[5];
    const float* bv    = (const float*)d_in[6];
    const float* gamma = (const float*)d_in[7];
    const float* beta  = (const float*)d_in[8];
    const float* W1    = (const float*)d_in[9];
    const float* b1    = (const float*)d_in[10];
    const float* W2    = (const float*)d_in[11];
    const float* b2    = (const float*)d_in[12];
    float* out = (float*)d_out;

    __half *Eh, *QKVh, *Sh, *Xh, *Hh, *Wqkvth, *W1th, *W2th, *Vth;
    float *S, *AE, *bqkv;
    cudaGetSymbolAddress((void**)&Eh,     g_Eh);
    cudaGetSymbolAddress((void**)&QKVh,   g_QKVh);
    cudaGetSymbolAddress((void**)&S,      g_S);
    cudaGetSymbolAddress((void**)&Sh,     g_Sh);
    cudaGetSymbolAddress((void**)&AE,     g_AE);
    cudaGetSymbolAddress((void**)&Xh,     g_Xh);
    cudaGetSymbolAddress((void**)&Hh,     g_Hh);
    cudaGetSymbolAddress((void**)&Wqkvth, g_Wqkvth);
    cudaGetSymbolAddress((void**)&W1th,   g_W1th);
    cudaGetSymbolAddress((void**)&W2th,   g_W2th);
    cudaGetSymbolAddress((void**)&Vth,    g_Vth);
    cudaGetSymbolAddress((void**)&bqkv,   g_bqkv);

    dim3 tb(32, 8);
    f2h<<<(NT * DM / 4 + 255) / 256, 256>>>(E, Eh, NT * DM / 4);
    transpose_f2h<<<dim3(DM / 32, DM / 32), tb>>>(Wq, Wqkvth,             DM, DM);
    transpose_f2h<<<dim3(DM / 32, DM / 32), tb>>>(Wk, Wqkvth + 1024 * DM, DM, DM);
    transpose_f2h<<<dim3(DM / 32, DM / 32), tb>>>(Wv, Wqkvth + 2048 * DM, DM, DM);
    transpose_f2h<<<dim3(DF / 32, DM / 32), tb>>>(W1, W1th,               DF, DM);
    transpose_f2h<<<dim3(DM / 32, DF / 32), tb>>>(W2, W2th,               DM, DF);
    cudaMemcpyAsync(bqkv,        bq, DM * sizeof(float), cudaMemcpyDeviceToDevice);
    cudaMemcpyAsync(bqkv + 1024, bk, DM * sizeof(float), cudaMemcpyDeviceToDevice);
    cudaMemcpyAsync(bqkv + 2048, bv, DM * sizeof(float), cudaMemcpyDeviceToDevice);

    dim3 blk(256);

    // fused QKV projection -> half [4096, 3072]
    hgemm2<false, false, false, true, true><<<dim3(3072 / 128, NT / 128), blk>>>(
        Eh, Wqkvth, bqkv, QKVh, 3072, DM, DM, DM, 1.f);

    // S = Q @ K^T / 32 (causal lower blocks) -> fp32
    hgemm2<true, false, false, false, false><<<dim3(NT / 128, NT / 128), blk>>>(
        QKVh, QKVh + 1024, nullptr, S, NT, DM, 3072, 3072, 0.03125f);

    softmax_causal<<<NT, 256>>>(S, Sh);

    // Vth[d][t] = V[t][d]
    transpose_h2h<<<dim3(DM / 32, NT / 32), tb>>>(QKVh + 2048, Vth, 3072, NT);

    // AE = probs @ V (triangular K) -> fp32
    hgemm2<false, true, false, false, false><<<dim3(DM / 128, NT / 128), blk>>>(
        Sh, Vth, nullptr, AE, DM, NT, NT, NT, 1.f);

    add_layernorm<<<NT, 256>>>(AE, E, gamma, beta, Xh);

    // FFN
    hgemm2<false, false, true, true, true><<<dim3(DF / 128, NT / 128), blk>>>(
        Xh, W1th, b1, Hh, DF, DM, DM, DM, 1.f);
    hgemm2<false, false, false, true, false><<<dim3(DM / 128, NT / 128), blk>>>(
        Hh, W2th, b2, out, DM, DF, DF, DF, 1.f);
}